// round 4
// baseline (speedup 1.0000x reference)
#include <cuda_runtime.h>
#include <cuda_bf16.h>
#include <math.h>

// Problem constants (compile-time, from reference)
#define T_STEPS 128
#define F_DIM   3
#define MATPTS  16
#define L_DIM   48

// Material constants computed in double at compile time, stored as float
__device__ __constant__ float c_dummy; // (placeholder, no dynamic constants needed)

static constexpr double E_MOD_D = 3130.0;
static constexpr double NU_D    = 0.37;
static constexpr double MU_D    = E_MOD_D / (2.0 * (1.0 + NU_D));
static constexpr double LAM_D   = E_MOD_D * NU_D / ((1.0 + NU_D) * (1.0 - 2.0 * NU_D));
static constexpr double HISO_D  = 300.0;
static constexpr double SIGY_D  = 64.8;

#define MUf      ((float)MU_D)
#define TWO_MUf  ((float)(2.0 * MU_D))
#define LAMf     ((float)LAM_D)
#define SIG_Yf   ((float)SIGY_D)
#define H_ISOf   ((float)HISO_D)
#define INV_DENf ((float)(1.0 / (3.0 * MU_D + HISO_D)))

// One thread = one material point for the whole T-loop.
// Lanes [16k, 16k+15] of a warp serve batch row b = gtid>>4; lane's point index m = gtid&15.
__global__ void __launch_bounds__(256, 8)
prnn_j2_kernel(const float* __restrict__ x,    // [B, T, 3]
               const float* __restrict__ W1,   // [48, 3]
               const float* __restrict__ W2,   // [3, 48]
               float* __restrict__ out,        // [B, T, 3]
               int B)
{
    const int gtid = blockIdx.x * blockDim.x + threadIdx.x;
    const int b = gtid >> 4;
    const int m = gtid & 15;
    if (b >= B) return;   // never taken for B=16384 (exact grid); warps stay full

    // W1 rows 3m..3m+2 : eps_r = sum_f w1[r][f] * x_f
    float w1_00 = __ldg(&W1[(3*m + 0)*3 + 0]);
    float w1_01 = __ldg(&W1[(3*m + 0)*3 + 1]);
    float w1_02 = __ldg(&W1[(3*m + 0)*3 + 2]);
    float w1_10 = __ldg(&W1[(3*m + 1)*3 + 0]);
    float w1_11 = __ldg(&W1[(3*m + 1)*3 + 1]);
    float w1_12 = __ldg(&W1[(3*m + 1)*3 + 2]);
    float w1_20 = __ldg(&W1[(3*m + 2)*3 + 0]);
    float w1_21 = __ldg(&W1[(3*m + 2)*3 + 1]);
    float w1_22 = __ldg(&W1[(3*m + 2)*3 + 2]);

    // softplus(W2)[o, 3m + c] for o,c in 0..2 (stable softplus)
    float w2s[3][3];
    #pragma unroll
    for (int o = 0; o < 3; o++) {
        #pragma unroll
        for (int c = 0; c < 3; c++) {
            float w = __ldg(&W2[o * L_DIM + 3*m + c]);
            w2s[o][c] = fmaxf(w, 0.0f) + log1pf(__expf(-fabsf(w)));
        }
    }

    // Committed history lives entirely in registers
    float pxx = 0.0f, pyy = 0.0f, pzz = 0.0f, pxy = 0.0f, alpha = 0.0f;

    const float* xb = x   + (size_t)b * (T_STEPS * 3);
    float*       ob = out + (size_t)b * (T_STEPS * 3);

    #pragma unroll 2
    for (int t = 0; t < T_STEPS; t++) {
        // all 16 lanes of the half-warp load the same 12 bytes -> broadcast
        float x0 = __ldg(&xb[3*t + 0]);
        float x1 = __ldg(&xb[3*t + 1]);
        float x2 = __ldg(&xb[3*t + 2]);

        // fc1: this point's strain (exx, eyy, gamma_xy)
        float exx = fmaf(w1_02, x2, fmaf(w1_01, x1, w1_00 * x0));
        float eyy = fmaf(w1_12, x2, fmaf(w1_11, x1, w1_10 * x0));
        float gxy = fmaf(w1_22, x2, fmaf(w1_21, x1, w1_20 * x0));

        // elastic predictor
        float ee_xx = exx - pxx;
        float ee_yy = eyy - pyy;
        float ee_zz = -pzz;
        float ee_xy = fmaf(0.5f, gxy, -pxy);
        float tr    = ee_xx + ee_yy + ee_zz;
        float ltr   = LAMf * tr;
        float sxx   = fmaf(TWO_MUf, ee_xx, ltr);
        float syy   = fmaf(TWO_MUf, ee_yy, ltr);
        float szz   = fmaf(TWO_MUf, ee_zz, ltr);
        float sxy   = TWO_MUf * ee_xy;

        float p   = (sxx + syy + szz) * (1.0f / 3.0f);
        float dxx = sxx - p, dyy = syy - p, dzz = szz - p;

        // q^2 = 1.5*(dxx^2+dyy^2+dzz^2+2*sxy^2)
        float ss  = fmaf(dxx, dxx, fmaf(dyy, dyy, fmaf(dzz, dzz, 2.0f * sxy * sxy)));
        float q2  = 1.5f * ss;
        float inv_q = __frsqrt_rn(fmaxf(q2, 1e-24f));
        float q     = q2 * inv_q;                      // = sqrt(q2), 0 when q2==0

        // radial return (closed form). c = dgam * 1.5 / qs (exactly 0 if no yield)
        float f    = q - fmaf(H_ISOf, alpha, SIG_Yf);
        float dgam = fmaxf(f, 0.0f) * INV_DENf;
        float csc  = 1.5f * dgam * inv_q;
        float k    = TWO_MUf * csc;

        float s0 = fmaf(-k, dxx, sxx);
        float s1 = fmaf(-k, dyy, syy);
        float s2 = fmaf(-k, sxy, sxy);

        // commit history
        pxx = fmaf(csc, dxx, pxx);
        pyy = fmaf(csc, dyy, pyy);
        pzz = fmaf(csc, dzz, pzz);
        pxy = fmaf(csc, sxy, pxy);
        alpha += dgam;

        // fc2 partials: this point's contribution to out[b,t,:]
        float a0 = fmaf(w2s[0][2], s2, fmaf(w2s[0][1], s1, w2s[0][0] * s0));
        float a1 = fmaf(w2s[1][2], s2, fmaf(w2s[1][1], s1, w2s[1][0] * s0));
        float a2 = fmaf(w2s[2][2], s2, fmaf(w2s[2][1], s1, w2s[2][0] * s0));

        // sum across the 16 points of this batch row (butterfly, stays in half-warp)
        #pragma unroll
        for (int off = 8; off > 0; off >>= 1) {
            a0 += __shfl_xor_sync(0xFFFFFFFFu, a0, off);
            a1 += __shfl_xor_sync(0xFFFFFFFFu, a1, off);
            a2 += __shfl_xor_sync(0xFFFFFFFFu, a2, off);
        }

        // lanes 0,1,2 of the half-warp each write one component -> one 12B txn per row
        if (m == 0) ob[3*t + 0] = a0;
        if (m == 1) ob[3*t + 1] = a1;
        if (m == 2) ob[3*t + 2] = a2;
    }
}

extern "C" void kernel_launch(void* const* d_in, const int* in_sizes, int n_in,
                              void* d_out, int out_size)
{
    const float* x  = (const float*)d_in[0];   // [B, T, 3]
    const float* W1 = (const float*)d_in[1];   // [48, 3]
    const float* W2 = (const float*)d_in[2];   // [3, 48]
    float* out = (float*)d_out;                // [B, T, 3]

    const int B = in_sizes[0] / (T_STEPS * F_DIM);
    const int P = B * MATPTS;                  // total material points = total threads

    const int threads = 256;
    const int blocks  = (P + threads - 1) / threads;
    prnn_j2_kernel<<<blocks, threads>>>(x, W1, W2, out, B);
}

// round 5
// speedup vs baseline: 1.3366x; 1.3366x over previous
#include <cuda_runtime.h>
#include <cuda_bf16.h>
#include <math.h>

// Problem constants (compile-time, from reference)
#define T_STEPS 128
#define F_DIM   3
#define MATPTS  16
#define L_DIM   48
#define MPT     2           // material points per thread
#define LPR     (MATPTS/MPT) // lanes per batch row = 8

static constexpr double E_MOD_D = 3130.0;
static constexpr double NU_D    = 0.37;
static constexpr double MU_D    = E_MOD_D / (2.0 * (1.0 + NU_D));
static constexpr double LAM_D   = E_MOD_D * NU_D / ((1.0 + NU_D) * (1.0 - 2.0 * NU_D));
static constexpr double HISO_D  = 300.0;
static constexpr double SIGY_D  = 64.8;

#define TWO_MUf  ((float)(2.0 * MU_D))
#define LAMf     ((float)LAM_D)
#define SIG_Yf   ((float)SIGY_D)
#define H_ISOf   ((float)HISO_D)
#define INV_DENf ((float)(1.0 / (3.0 * MU_D + HISO_D)))

// One thread owns MPT=2 material points of one batch row for all 128 steps.
// Lanes [8k .. 8k+7] of a warp serve batch row b = gtid>>3; lane owns points
// 2m, 2m+1 (m = gtid&7). All committed history lives in registers.
__global__ void __launch_bounds__(128, 6)
prnn_j2_kernel(const float* __restrict__ x,    // [B, T, 3]
               const float* __restrict__ W1,   // [48, 3]
               const float* __restrict__ W2,   // [3, 48]
               float* __restrict__ out,        // [B, T, 3]
               int B)
{
    const int gtid = blockIdx.x * blockDim.x + threadIdx.x;
    const int b = gtid >> 3;
    const int m = gtid & 7;
    if (b >= B) return;   // exact grid for B=16384; warps stay full

    // Per-point weights: W1 rows 3*pt .. 3*pt+2 and softplus(W2) columns 3*pt .. 3*pt+2
    float w1[MPT][9];
    float w2s[MPT][3][3];
    #pragma unroll
    for (int j = 0; j < MPT; j++) {
        const int pt = MPT * m + j;
        #pragma unroll
        for (int r = 0; r < 3; r++)
            #pragma unroll
            for (int c = 0; c < 3; c++)
                w1[j][3*r + c] = __ldg(&W1[(3*pt + r)*3 + c]);
        #pragma unroll
        for (int o = 0; o < 3; o++)
            #pragma unroll
            for (int c = 0; c < 3; c++) {
                float w = __ldg(&W2[o * L_DIM + 3*pt + c]);
                // stable softplus
                w2s[j][o][c] = fmaxf(w, 0.0f) + log1pf(__expf(-fabsf(w)));
            }
    }

    // Committed history (registers)
    float pxx[MPT], pyy[MPT], pzz[MPT], pxy[MPT], alpha[MPT];
    #pragma unroll
    for (int j = 0; j < MPT; j++) { pxx[j]=0.f; pyy[j]=0.f; pzz[j]=0.f; pxy[j]=0.f; alpha[j]=0.f; }

    // x row is 16B aligned: b * 384 floats = b * 1536 bytes
    const float4* __restrict__ xb4 = (const float4*)(x + (size_t)b * (T_STEPS * 3));
    float* __restrict__ ob = out + (size_t)b * (T_STEPS * 3);

    for (int tb = 0; tb < T_STEPS / 4; tb++) {
        // 4 timesteps = 12 floats = 3 x LDG.128 (broadcast across the 8 lanes of this row)
        float4 v0 = __ldg(&xb4[3*tb + 0]);
        float4 v1 = __ldg(&xb4[3*tb + 1]);
        float4 v2 = __ldg(&xb4[3*tb + 2]);
        float xs[12] = { v0.x, v0.y, v0.z, v0.w,
                         v1.x, v1.y, v1.z, v1.w,
                         v2.x, v2.y, v2.z, v2.w };

        #pragma unroll
        for (int s = 0; s < 4; s++) {
            const float x0 = xs[3*s + 0];
            const float x1 = xs[3*s + 1];
            const float x2 = xs[3*s + 2];

            float a0 = 0.0f, a1 = 0.0f, a2 = 0.0f;

            #pragma unroll
            for (int j = 0; j < MPT; j++) {
                // fc1: this point's strain
                float exx = fmaf(w1[j][2], x2, fmaf(w1[j][1], x1, w1[j][0] * x0));
                float eyy = fmaf(w1[j][5], x2, fmaf(w1[j][4], x1, w1[j][3] * x0));
                float gxy = fmaf(w1[j][8], x2, fmaf(w1[j][7], x1, w1[j][6] * x0));

                // elastic predictor
                float ee_xx = exx - pxx[j];
                float ee_yy = eyy - pyy[j];
                float ee_zz = -pzz[j];
                float ee_xy = fmaf(0.5f, gxy, -pxy[j]);
                float tr    = ee_xx + ee_yy + ee_zz;
                float ltr   = LAMf * tr;
                float sxx   = fmaf(TWO_MUf, ee_xx, ltr);
                float syy   = fmaf(TWO_MUf, ee_yy, ltr);
                float szz   = fmaf(TWO_MUf, ee_zz, ltr);
                float sxy   = TWO_MUf * ee_xy;

                float p   = (sxx + syy + szz) * (1.0f / 3.0f);
                float dxx = sxx - p, dyy = syy - p, dzz = szz - p;

                // q^2 = 1.5*(dev:dev)
                float ss  = fmaf(dxx, dxx, fmaf(dyy, dyy, fmaf(dzz, dzz, 2.0f * sxy * sxy)));
                float q2  = 1.5f * ss;
                float inv_q = __frsqrt_rn(fmaxf(q2, 1e-24f));
                float q     = q2 * inv_q;

                // radial return (closed form); csc == 0 exactly when no yield
                float f    = q - fmaf(H_ISOf, alpha[j], SIG_Yf);
                float dgam = fmaxf(f, 0.0f) * INV_DENf;
                float csc  = 1.5f * dgam * inv_q;
                float k    = TWO_MUf * csc;

                float s0 = fmaf(-k, dxx, sxx);
                float s1 = fmaf(-k, dyy, syy);
                float s2 = fmaf(-k, sxy, sxy);

                // commit history
                pxx[j] = fmaf(csc, dxx, pxx[j]);
                pyy[j] = fmaf(csc, dyy, pyy[j]);
                pzz[j] = fmaf(csc, dzz, pzz[j]);
                pxy[j] = fmaf(csc, sxy, pxy[j]);
                alpha[j] += dgam;

                // fc2 partials, accumulated across this thread's points
                a0 = fmaf(w2s[j][0][0], s0, fmaf(w2s[j][0][1], s1, fmaf(w2s[j][0][2], s2, a0)));
                a1 = fmaf(w2s[j][1][0], s0, fmaf(w2s[j][1][1], s1, fmaf(w2s[j][1][2], s2, a1)));
                a2 = fmaf(w2s[j][2][0], s0, fmaf(w2s[j][2][1], s1, fmaf(w2s[j][2][2], s2, a2)));
            }

            // reduce across the 8 lanes of this batch row (3 stages x 3 comps = 9 SHFL)
            #pragma unroll
            for (int off = 4; off > 0; off >>= 1) {
                a0 += __shfl_xor_sync(0xFFFFFFFFu, a0, off);
                a1 += __shfl_xor_sync(0xFFFFFFFFu, a1, off);
                a2 += __shfl_xor_sync(0xFFFFFFFFu, a2, off);
            }

            // single STG per timestep: lanes 0,1,2 write components 0,1,2
            float v = (m == 0) ? a0 : ((m == 1) ? a1 : a2);
            if (m < 3) ob[3*(4*tb + s) + m] = v;
        }
    }
}

extern "C" void kernel_launch(void* const* d_in, const int* in_sizes, int n_in,
                              void* d_out, int out_size)
{
    const float* x  = (const float*)d_in[0];   // [B, T, 3]
    const float* W1 = (const float*)d_in[1];   // [48, 3]
    const float* W2 = (const float*)d_in[2];   // [3, 48]
    float* out = (float*)d_out;                // [B, T, 3]

    const int B = in_sizes[0] / (T_STEPS * F_DIM);
    const int total_threads = B * LPR;         // one thread per 2 material points

    const int threads = 128;
    const int blocks  = (total_threads + threads - 1) / threads;
    prnn_j2_kernel<<<blocks, threads>>>(x, W1, W2, out, B);
}